// round 4
// baseline (speedup 1.0000x reference)
#include <cuda_runtime.h>
#include <cuda_bf16.h>
#include <math.h>
#include <stdint.h>

#define BATCH 262144
#define HID 512
#define NDIM 12
#define TRI 78
#define OUTC 79

typedef __nv_bfloat16 bf16;
typedef __nv_bfloat162 bf162;

// Packed operand layout: row-major, width 1024 bf16 per row.
// col offset for k: (k/32)*64 + (k%32) -> hi plane; +32 -> lo plane.
__device__ bf16 g_h2pk[(size_t)BATCH * 1024];   // 512 MB
__device__ bf16 g_w2pk[(size_t)HID * 1024];     // 1 MB   (rows = out-col n)
__device__ bf16 g_w3pk[(size_t)128 * 1024];     // 256 KB (rows n, zero-pad >=79)

#define SWZ(o) ((o) ^ (((o) >> 3) & 0x70))

__device__ __forceinline__ uint32_t smem_u32(const void* p) {
    uint32_t a;
    asm("{ .reg .u64 t; cvta.to.shared.u64 t, %1; cvt.u32.u64 %0, t; }"
        : "=r"(a) : "l"(p));
    return a;
}
__device__ __forceinline__ void cp16(uint32_t dst, const void* src) {
    asm volatile("cp.async.cg.shared.global [%0], [%1], 16;"
                 :: "r"(dst), "l"(src));
}
#define CP_COMMIT() asm volatile("cp.async.commit_group;" ::: "memory")
#define CP_WAIT(n)  asm volatile("cp.async.wait_group %0;" :: "n"(n) : "memory")

#define LDSM_X4(r0, r1, r2, r3, a)                                            \
    asm volatile("ldmatrix.sync.aligned.m8n8.x4.shared.b16 {%0,%1,%2,%3}, [%4];" \
                 : "=r"(r0), "=r"(r1), "=r"(r2), "=r"(r3) : "r"(a))
#define LDSM_X2(r0, r1, a)                                                    \
    asm volatile("ldmatrix.sync.aligned.m8n8.x2.shared.b16 {%0,%1}, [%2];"    \
                 : "=r"(r0), "=r"(r1) : "r"(a))
#define MMA_BF16(c, a, b)                                                     \
    asm volatile("mma.sync.aligned.m16n8k16.row.col.f32.bf16.bf16.f32 "       \
                 "{%0,%1,%2,%3}, {%4,%5,%6,%7}, {%8,%9}, {%0,%1,%2,%3};"      \
                 : "+f"((c)[0]), "+f"((c)[1]), "+f"((c)[2]), "+f"((c)[3])     \
                 : "r"((a)[0]), "r"((a)[1]), "r"((a)[2]), "r"((a)[3]),        \
                   "r"((b)[0]), "r"((b)[1]))

static __device__ __forceinline__ float softplusf(float v) {
    return (v > 20.f) ? v : log1pf(expf(v));
}
static __device__ __forceinline__ int pkoff(int k) {
    return ((k >> 5) << 6) + (k & 31);
}

// ---------------- weight converters (transpose + hi/lo split + pack) --------
__global__ __launch_bounds__(256) void conv_w2(const float* __restrict__ W2) {
    int t = blockIdx.x * 256 + threadIdx.x;        // < 512*512
    int n = t >> 9, k = t & 511;
    float v = W2[(size_t)k * HID + n];
    bf16 h = __float2bfloat16(v);
    size_t o = (size_t)n * 1024 + pkoff(k);
    g_w2pk[o] = h;
    g_w2pk[o + 32] = __float2bfloat16(v - __bfloat162float(h));
}
__global__ __launch_bounds__(256) void conv_w3(const float* __restrict__ W3) {
    int t = blockIdx.x * 256 + threadIdx.x;        // < 128*512
    int n = t >> 9, k = t & 511;
    float v = (n < OUTC) ? W3[(size_t)k * OUTC + n] : 0.f;
    bf16 h = __float2bfloat16(v);
    size_t o = (size_t)n * 1024 + pkoff(k);
    g_w3pk[o] = h;
    g_w3pk[o + 32] = __float2bfloat16(v - __bfloat162float(h));
}

// ---------------------------------------------------------------------------
// Fused layer1 + layer2 GEMM.
// Per CTA: compute h1 tile (128 x 512) on the fly from x/W1/b1 (FFMA, K=12),
// split to bf16 hi/lo into swizzled smem A groups (64 cols = 2 k-chunks),
// stream B = W2pk slice via double-buffered cp.async, 3-term bf16 mma.sync.
// Epilogue: relu -> packed hi/lo h2 write.
// smem: [0,64K) B double buffer; [64K, 96K) A group; [96K, +6.5K) x tile.
// ---------------------------------------------------------------------------
__global__ __launch_bounds__(256, 2) void fused_l12(
    const float* __restrict__ x, const float* __restrict__ W1,
    const float* __restrict__ b1, const bf16* __restrict__ Bpk,
    const float* __restrict__ bias, bf16* __restrict__ Opk)
{
    extern __shared__ char smem[];
    const uint32_t sb = smem_u32(smem);
    const uint32_t sbA = sb + 65536;
    float* xs = (float*)(smem + 98304);          // 128 x 13 (padded)

    const int tid = threadIdx.x;
    const int lane = tid & 31;
    const int wid = tid >> 5;
    const int wm = wid >> 2;
    const int wn = wid & 3;
    const int m0 = blockIdx.y * 128;
    const int n0 = blockIdx.x * 128;

    // ---- load x tile to smem (padded stride 13) ----
    for (int i = tid; i < 128 * NDIM; i += 256) {
        int r = i / NDIM, c = i - r * NDIM;
        xs[r * 13 + c] = x[(size_t)(m0 + r) * NDIM + c];
    }

    const bf16* Bbase = Bpk + (size_t)n0 * 1024;

    // issue B group 0 (chunks 0,1)
    auto load_bgroup = [&](int g) {
        uint32_t bb = sb + (g & 1) * 32768;
        const bf16* Bs = Bbase + g * 128;        // 2 chunks = 128 packed cols
#pragma unroll
        for (int it = 0; it < 8; ++it) {
            int u = tid + it * 256;              // 0..2047
            int ci = u >> 10;
            int v = u & 1023;
            int r = v >> 3, q = v & 7;
            cp16(bb + ci * 16384 + SWZ(r * 128 + q * 16),
                 Bs + (size_t)r * 1024 + ci * 64 + q * 8);
        }
        CP_COMMIT();
    };
    load_bgroup(0);

    __syncthreads();   // x ready

    // per-thread x row cached in registers
    const int rr = tid & 127;
    const int cHalf = (tid >> 7) * 32;
    float xv[NDIM];
#pragma unroll
    for (int k = 0; k < NDIM; ++k) xv[k] = xs[rr * 13 + k];

    float acc[4][4][4];
#pragma unroll
    for (int i = 0; i < 4; i++)
#pragma unroll
        for (int j = 0; j < 4; j++)
#pragma unroll
            for (int k = 0; k < 4; k++) acc[i][j][k] = 0.f;

    for (int g = 0; g < 8; ++g) {
        if (g) __syncthreads();                  // prev MMA done with A + B buf
        if (g < 7) load_bgroup(g + 1);

        // ---- FFMA fill A group g: h1 cols [g*64, g*64+64) ----
#pragma unroll
        for (int jj = 0; jj < 32; jj += 2) {
            const int cl = cHalf + jj;           // local col 0..63
            const int gc = g * 64 + cl;
            float a0 = __ldg(b1 + gc), a1 = __ldg(b1 + gc + 1);
#pragma unroll
            for (int k = 0; k < NDIM; ++k) {
                a0 = fmaf(xv[k], __ldg(W1 + k * HID + gc), a0);
                a1 = fmaf(xv[k], __ldg(W1 + k * HID + gc + 1), a1);
            }
            a0 = fmaxf(a0, 0.f); a1 = fmaxf(a1, 0.f);
            bf16 h0 = __float2bfloat16(a0), h1 = __float2bfloat16(a1);
            bf16 l0 = __float2bfloat16(a0 - __bfloat162float(h0));
            bf16 l1 = __float2bfloat16(a1 - __bfloat162float(h1));
            const int ci = cl >> 5, kin = cl & 31;
            char* base = smem + 65536 + ci * 16384;
            *(bf162*)(base + SWZ(rr * 128 + kin * 2)) = __halves2bfloat162(h0, h1);
            *(bf162*)(base + SWZ(rr * 128 + 64 + kin * 2)) = __halves2bfloat162(l0, l1);
        }

        if (g < 7) { CP_WAIT(1); } else { CP_WAIT(0); }
        __syncthreads();                         // A filled + B(g) visible

        const uint32_t bbuf = sb + (g & 1) * 32768;
#pragma unroll
        for (int ci = 0; ci < 2; ++ci) {
            const uint32_t ab = sbA + ci * 16384;
            const uint32_t bb = bbuf + ci * 16384;
#pragma unroll
            for (int ks = 0; ks < 2; ++ks) {
                uint32_t bfr[2][4][2];
                const int brow0 = wn * 32 + (lane & 7);
                const int bsel = (lane >> 3) & 1;
#pragma unroll
                for (int pl = 0; pl < 2; ++pl)
#pragma unroll
                    for (int nt = 0; nt < 4; ++nt) {
                        int row = brow0 + nt * 8;
                        int seg = pl * 4 + ks * 2 + bsel;
                        LDSM_X2(bfr[pl][nt][0], bfr[pl][nt][1],
                                bb + row * 128 + ((seg ^ (row & 7)) << 4));
                    }
#pragma unroll
                for (int mt = 0; mt < 4; ++mt) {
                    uint32_t afr[2][4];
                    const int arow = wm * 64 + mt * 16 + (lane & 15);
                    const int asel = lane >> 4;
#pragma unroll
                    for (int pl = 0; pl < 2; ++pl) {
                        int seg = pl * 4 + ks * 2 + asel;
                        LDSM_X4(afr[pl][0], afr[pl][1], afr[pl][2], afr[pl][3],
                                ab + arow * 128 + ((seg ^ (arow & 7)) << 4));
                    }
#pragma unroll
                    for (int nt = 0; nt < 4; ++nt)
                        MMA_BF16(acc[mt][nt], afr[0], bfr[0][nt]);   // hi*hi
#pragma unroll
                    for (int nt = 0; nt < 4; ++nt)
                        MMA_BF16(acc[mt][nt], afr[0], bfr[1][nt]);   // hi*lo
#pragma unroll
                    for (int nt = 0; nt < 4; ++nt)
                        MMA_BF16(acc[mt][nt], afr[1], bfr[0][nt]);   // lo*hi
                }
            }
        }
    }

    // ---- epilogue: relu -> packed hi/lo h2 ----
    const int r0 = wm * 64 + (lane >> 2);
    const int c0 = wn * 32 + (lane & 3) * 2;
#pragma unroll
    for (int mt = 0; mt < 4; ++mt)
#pragma unroll
        for (int nt = 0; nt < 4; ++nt) {
            const int gc = n0 + c0 + nt * 8;
            const float bb0 = __ldg(bias + gc);
            const float bb1 = __ldg(bias + gc + 1);
#pragma unroll
            for (int h = 0; h < 2; ++h) {
                const int row = m0 + r0 + mt * 16 + 8 * h;
                float v0 = fmaxf(acc[mt][nt][2 * h] + bb0, 0.f);
                float v1 = fmaxf(acc[mt][nt][2 * h + 1] + bb1, 0.f);
                bf16 h0 = __float2bfloat16(v0), h1 = __float2bfloat16(v1);
                bf16 l0 = __float2bfloat16(v0 - __bfloat162float(h0));
                bf16 l1 = __float2bfloat16(v1 - __bfloat162float(h1));
                size_t off = (size_t)row * 1024 + pkoff(gc);
                *(bf162*)(Opk + off)      = __halves2bfloat162(h0, h1);
                *(bf162*)(Opk + off + 32) = __halves2bfloat162(l0, l1);
            }
        }
}

// ---------------------------------------------------------------------------
// GEMM3: softplus(h2 @ W3^T + b3) fused with L@L^T + c  (as R3, ACT=2)
// ---------------------------------------------------------------------------
__global__ __launch_bounds__(256, 2) void gemm3_mmt(
    const bf16* __restrict__ Apk, const bf16* __restrict__ Bpk,
    const float* __restrict__ bias, float* __restrict__ dst)
{
    extern __shared__ char smem[];
    const uint32_t sb = smem_u32(smem);
    const int tid = threadIdx.x;
    const int lane = tid & 31;
    const int wid = tid >> 5;
    const int wm = wid >> 2;
    const int wn = wid & 3;
    const int m0 = blockIdx.y * 128;

    float acc[4][4][4];
#pragma unroll
    for (int i = 0; i < 4; i++)
#pragma unroll
        for (int j = 0; j < 4; j++)
#pragma unroll
            for (int k = 0; k < 4; k++) acc[i][j][k] = 0.f;

    const bf16* Abase = Apk + (size_t)m0 * 1024;
    const bf16* Bbase = Bpk;

    auto load_chunk = [&](int c, int buf) {
        uint32_t ab = sb + (buf ? 16384 : 0);
        uint32_t bb = sb + 32768 + (buf ? 16384 : 0);
        const bf16* As = Abase + c * 64;
        const bf16* Bs = Bbase + c * 64;
#pragma unroll
        for (int it = 0; it < 8; ++it) {
            int u = tid + it * 256;
            int half = u >> 10;
            int v = u & 1023;
            int r = v >> 3, q = v & 7;
            const bf16* s = (half ? Bs : As) + (size_t)r * 1024 + q * 8;
            cp16((half ? bb : ab) + SWZ(r * 128 + q * 16), s);
        }
        CP_COMMIT();
    };

    load_chunk(0, 0);

    for (int c = 0; c < 16; ++c) {
        CP_WAIT(0);
        __syncthreads();
        if (c < 15) load_chunk(c + 1, (c + 1) & 1);

        const int buf = c & 1;
        const uint32_t ab = sb + (buf ? 16384 : 0);
        const uint32_t bb = sb + 32768 + (buf ? 16384 : 0);

#pragma unroll
        for (int ks = 0; ks < 2; ++ks) {
            uint32_t bfr[2][4][2];
            const int brow0 = wn * 32 + (lane & 7);
            const int bsel = (lane >> 3) & 1;
#pragma unroll
            for (int pl = 0; pl < 2; ++pl)
#pragma unroll
                for (int nt = 0; nt < 4; ++nt) {
                    int row = brow0 + nt * 8;
                    int seg = pl * 4 + ks * 2 + bsel;
                    LDSM_X2(bfr[pl][nt][0], bfr[pl][nt][1],
                            bb + row * 128 + ((seg ^ (row & 7)) << 4));
                }
#pragma unroll
            for (int mt = 0; mt < 4; ++mt) {
                uint32_t afr[2][4];
                const int arow = wm * 64 + mt * 16 + (lane & 15);
                const int asel = lane >> 4;
#pragma unroll
                for (int pl = 0; pl < 2; ++pl) {
                    int seg = pl * 4 + ks * 2 + asel;
                    LDSM_X4(afr[pl][0], afr[pl][1], afr[pl][2], afr[pl][3],
                            ab + arow * 128 + ((seg ^ (arow & 7)) << 4));
                }
#pragma unroll
                for (int nt = 0; nt < 4; ++nt)
                    MMA_BF16(acc[mt][nt], afr[0], bfr[0][nt]);
#pragma unroll
                for (int nt = 0; nt < 4; ++nt)
                    MMA_BF16(acc[mt][nt], afr[0], bfr[1][nt]);
#pragma unroll
                for (int nt = 0; nt < 4; ++nt)
                    MMA_BF16(acc[mt][nt], afr[1], bfr[0][nt]);
            }
        }
        __syncthreads();
    }

    // ---- epilogue: softplus -> smem stage -> L@L^T + c ----
    const int r0 = wm * 64 + (lane >> 2);
    const int c0 = wn * 32 + (lane & 3) * 2;
    float* stage = (float*)smem;
#pragma unroll
    for (int mt = 0; mt < 4; ++mt)
#pragma unroll
        for (int nt = 0; nt < 4; ++nt) {
            const int col = c0 + nt * 8;
            if (col >= 80) continue;
#pragma unroll
            for (int h = 0; h < 2; ++h) {
                const int row = r0 + mt * 16 + 8 * h;
                if (col < OUTC)
                    stage[row * 81 + col] =
                        softplusf(acc[mt][nt][2 * h] + __ldg(bias + col));
                if (col + 1 < OUTC)
                    stage[row * 81 + col + 1] =
                        softplusf(acc[mt][nt][2 * h + 1] + __ldg(bias + col + 1));
            }
        }
    __syncthreads();

    for (int i = tid; i < 128 * 144; i += 256) {
        int r = i / 144;
        int e = i - r * 144;
        int ii = e / 12;
        int kk = e - ii * 12;
        int mn = ii < kk ? ii : kk;
        const float* Li = stage + r * 81 + ((ii * (ii + 1)) >> 1);
        const float* Lk = stage + r * 81 + ((kk * (kk + 1)) >> 1);
        float a = 0.f;
#pragma unroll 4
        for (int j = 0; j <= mn; ++j) a = fmaf(Li[j], Lk[j], a);
        dst[(size_t)m0 * 144 + i] = a;
    }
    if (tid < 128)
        dst[(size_t)BATCH * 144 + m0 + tid] = stage[tid * 81 + TRI];
}

// ---------------- launch ----------------------------------------------------
extern "C" void kernel_launch(void* const* d_in, const int* in_sizes, int n_in,
                              void* d_out, int out_size)
{
    const float* x  = (const float*)d_in[0];
    const float* W1 = (const float*)d_in[1];
    const float* b1 = (const float*)d_in[2];
    const float* W2 = (const float*)d_in[3];
    const float* b2 = (const float*)d_in[4];
    const float* W3 = (const float*)d_in[5];
    const float* b3 = (const float*)d_in[6];
    float* out = (float*)d_out;

    bf16 *h2pk, *w2pk, *w3pk;
    cudaGetSymbolAddress((void**)&h2pk, g_h2pk);
    cudaGetSymbolAddress((void**)&w2pk, g_w2pk);
    cudaGetSymbolAddress((void**)&w3pk, g_w3pk);

    conv_w2<<<(HID * HID) / 256, 256>>>(W2);
    conv_w3<<<(128 * HID) / 256, 256>>>(W3);

    constexpr int SMEM_F = 65536 + 32768 + 128 * 13 * 4;   // 104960
    constexpr int SMEM_3 = 65536;
    cudaFuncSetAttribute(fused_l12,
                         cudaFuncAttributeMaxDynamicSharedMemorySize, SMEM_F);
    cudaFuncSetAttribute(gemm3_mmt,
                         cudaFuncAttributeMaxDynamicSharedMemorySize, SMEM_3);

    // Fused layer1+2: h2 = relu(relu(x@W1+b1) @ W2 + b2)
    fused_l12<<<dim3(4, BATCH / 128), 256, SMEM_F>>>(x, W1, b1, w2pk, b2, h2pk);
    // Layer 3 fused: softplus + L@L^T + c
    gemm3_mmt<<<dim3(1, BATCH / 128), 256, SMEM_3>>>(h2pk, w3pk, b3, out);
}

// round 5
// speedup vs baseline: 1.4720x; 1.4720x over previous
#include <cuda_runtime.h>
#include <cuda_bf16.h>
#include <math.h>
#include <stdint.h>

#define BATCH 262144
#define HID 512
#define NDIM 12
#define TRI 78
#define OUTC 79

typedef __nv_bfloat16 bf16;
typedef __nv_bfloat162 bf162;

// Packed operand layout: row-major, width 1024 bf16 per row.
// col offset for k: (k/32)*64 + (k%32) -> hi plane; +32 -> lo plane.
__device__ bf16 g_h1pk[(size_t)BATCH * 1024];   // 512 MB
__device__ bf16 g_h2pk[(size_t)BATCH * 1024];   // 512 MB
__device__ bf16 g_w2pk[(size_t)HID * 1024];     // 1 MB   (rows = out-col n)
__device__ bf16 g_w3pk[(size_t)128 * 1024];     // 256 KB (rows n, zero-pad >=79)

#define SWZ(o) ((o) ^ (((o) >> 3) & 0x70))

__device__ __forceinline__ uint32_t smem_u32(const void* p) {
    uint32_t a;
    asm("{ .reg .u64 t; cvta.to.shared.u64 t, %1; cvt.u32.u64 %0, t; }"
        : "=r"(a) : "l"(p));
    return a;
}
__device__ __forceinline__ void cp16(uint32_t dst, const void* src) {
    asm volatile("cp.async.cg.shared.global [%0], [%1], 16;"
                 :: "r"(dst), "l"(src));
}
#define CP_COMMIT() asm volatile("cp.async.commit_group;" ::: "memory")
#define CP_WAIT(n)  asm volatile("cp.async.wait_group %0;" :: "n"(n) : "memory")

#define LDSM_X4(r0, r1, r2, r3, a)                                            \
    asm volatile("ldmatrix.sync.aligned.m8n8.x4.shared.b16 {%0,%1,%2,%3}, [%4];" \
                 : "=r"(r0), "=r"(r1), "=r"(r2), "=r"(r3) : "r"(a))
#define LDSM_X2(r0, r1, a)                                                    \
    asm volatile("ldmatrix.sync.aligned.m8n8.x2.shared.b16 {%0,%1}, [%2];"    \
                 : "=r"(r0), "=r"(r1) : "r"(a))
#define MMA_BF16(c, a, b)                                                     \
    asm volatile("mma.sync.aligned.m16n8k16.row.col.f32.bf16.bf16.f32 "       \
                 "{%0,%1,%2,%3}, {%4,%5,%6,%7}, {%8,%9}, {%0,%1,%2,%3};"      \
                 : "+f"((c)[0]), "+f"((c)[1]), "+f"((c)[2]), "+f"((c)[3])     \
                 : "r"((a)[0]), "r"((a)[1]), "r"((a)[2]), "r"((a)[3]),        \
                   "r"((b)[0]), "r"((b)[1]))

static __device__ __forceinline__ float softplusf(float v) {
    return (v > 20.f) ? v : log1pf(expf(v));
}
static __device__ __forceinline__ int pkoff(int k) {
    return ((k >> 5) << 6) + (k & 31);
}

// ---------------- weight converters (transpose + hi/lo split + pack) --------
__global__ __launch_bounds__(256) void conv_w2(const float* __restrict__ W2) {
    int t = blockIdx.x * 256 + threadIdx.x;        // < 512*512
    int n = t >> 9, k = t & 511;
    float v = W2[(size_t)k * HID + n];
    bf16 h = __float2bfloat16(v);
    size_t o = (size_t)n * 1024 + pkoff(k);
    g_w2pk[o] = h;
    g_w2pk[o + 32] = __float2bfloat16(v - __bfloat162float(h));
}
__global__ __launch_bounds__(256) void conv_w3(const float* __restrict__ W3) {
    int t = blockIdx.x * 256 + threadIdx.x;        // < 128*512
    int n = t >> 9, k = t & 511;
    float v = (n < OUTC) ? W3[(size_t)k * OUTC + n] : 0.f;
    bf16 h = __float2bfloat16(v);
    size_t o = (size_t)n * 1024 + pkoff(k);
    g_w3pk[o] = h;
    g_w3pk[o + 32] = __float2bfloat16(v - __bfloat162float(h));
}

// ---------------- layer 1 (K=12) — vectorized 16B stores --------------------
__global__ __launch_bounds__(256) void l1_kernel(
    const float* __restrict__ x, const float* __restrict__ W1,
    const float* __restrict__ b1, bf16* __restrict__ hpk)
{
    __shared__ float W1s[NDIM][HID];
    __shared__ float b1s[HID];
    __shared__ float xs[64][13];
    const int tid = threadIdx.x;
    const int b0 = blockIdx.x * 64;

    for (int i = tid; i < NDIM * HID; i += 256) W1s[i / HID][i % HID] = W1[i];
    for (int i = tid; i < HID; i += 256) b1s[i] = b1[i];
    for (int i = tid; i < 64 * NDIM; i += 256)
        xs[i / NDIM][i % NDIM] = x[(size_t)b0 * NDIM + i];
    __syncthreads();

    // 64 rows x 64 col-groups(8) = 4096 items, 16 iters
#pragma unroll 4
    for (int it = 0; it < 16; ++it) {
        int p = tid + it * 256;
        int r = p >> 6;
        int c = (p & 63) * 8;
        float a[8];
#pragma unroll
        for (int j = 0; j < 8; ++j) a[j] = b1s[c + j];
#pragma unroll
        for (int k = 0; k < NDIM; ++k) {
            float xv = xs[r][k];
#pragma unroll
            for (int j = 0; j < 8; ++j)
                a[j] = fmaf(xv, W1s[k][c + j], a[j]);
        }
        __align__(16) bf162 hb[4], lb[4];
#pragma unroll
        for (int j = 0; j < 4; ++j) {
            float v0 = fmaxf(a[2 * j], 0.f), v1 = fmaxf(a[2 * j + 1], 0.f);
            bf16 h0 = __float2bfloat16(v0), h1 = __float2bfloat16(v1);
            hb[j] = __halves2bfloat162(h0, h1);
            lb[j] = __halves2bfloat162(
                __float2bfloat16(v0 - __bfloat162float(h0)),
                __float2bfloat16(v1 - __bfloat162float(h1)));
        }
        size_t base = (size_t)(b0 + r) * 1024 + pkoff(c);
        *(uint4*)(hpk + base)      = *(uint4*)hb;
        *(uint4*)(hpk + base + 32) = *(uint4*)lb;
    }
}

// ---------------- mma.sync bf16 3-term-split GEMM, 3-stage pipeline ---------
// C[128m,128n] = act(A @ B^T + bias). A rows from Apk (m0+..), B rows (n0+..).
// ACT=1: relu -> packed hi/lo write to Opk.   ACT=2: softplus + L@L^T -> dst.
// smem: 3 stages x (16KB A + 16KB B) = 96KB.
template <int ACT>
__global__ __launch_bounds__(256, 2) void mma_gemm(
    const bf16* __restrict__ Apk, const bf16* __restrict__ Bpk,
    const float* __restrict__ bias,
    bf16* __restrict__ Opk, float* __restrict__ dst)
{
    extern __shared__ char smem[];
    const uint32_t sb = smem_u32(smem);
    const int tid = threadIdx.x;
    const int lane = tid & 31;
    const int wid = tid >> 5;
    const int wm = wid >> 2;        // 0..1  (m band of 64)
    const int wn = wid & 3;         // 0..3  (n band of 32)
    const int m0 = blockIdx.y * 128;
    const int n0 = blockIdx.x * 128;

    float acc[4][4][4];
#pragma unroll
    for (int i = 0; i < 4; i++)
#pragma unroll
        for (int j = 0; j < 4; j++)
#pragma unroll
            for (int k = 0; k < 4; k++) acc[i][j][k] = 0.f;

    const bf16* Abase = Apk + (size_t)m0 * 1024;
    const bf16* Bbase = Bpk + (size_t)n0 * 1024;

    auto load_chunk = [&](int c, int st) {
        uint32_t ab = sb + st * 32768;
        uint32_t bb = ab + 16384;
        const bf16* As = Abase + c * 64;
        const bf16* Bs = Bbase + c * 64;
#pragma unroll
        for (int it = 0; it < 8; ++it) {
            int u = tid + it * 256;              // 0..2047
            int half = u >> 10;
            int v = u & 1023;
            int r = v >> 3, q = v & 7;
            const bf16* s = (half ? Bs : As) + (size_t)r * 1024 + q * 8;
            cp16((half ? bb : ab) + SWZ(r * 128 + q * 16), s);
        }
        CP_COMMIT();
    };

    load_chunk(0, 0);
    load_chunk(1, 1);

    for (int c = 0; c < 16; ++c) {
        if (c == 15) { CP_WAIT(0); } else { CP_WAIT(1); }
        __syncthreads();
        if (c + 2 < 16) load_chunk(c + 2, (c + 2) % 3);

        const int st = c % 3;
        const uint32_t ab = sb + st * 32768;
        const uint32_t bb = ab + 16384;

#pragma unroll
        for (int ks = 0; ks < 2; ++ks) {
            uint32_t bfr[2][4][2];
            const int brow0 = wn * 32 + (lane & 7);
            const int bsel = (lane >> 3) & 1;
#pragma unroll
            for (int pl = 0; pl < 2; ++pl)
#pragma unroll
                for (int nt = 0; nt < 4; ++nt) {
                    int row = brow0 + nt * 8;
                    int seg = pl * 4 + ks * 2 + bsel;
                    LDSM_X2(bfr[pl][nt][0], bfr[pl][nt][1],
                            bb + row * 128 + ((seg ^ (row & 7)) << 4));
                }
#pragma unroll
            for (int mt = 0; mt < 4; ++mt) {
                uint32_t afr[2][4];
                const int arow = wm * 64 + mt * 16 + (lane & 15);
                const int asel = lane >> 4;
#pragma unroll
                for (int pl = 0; pl < 2; ++pl) {
                    int seg = pl * 4 + ks * 2 + asel;
                    LDSM_X4(afr[pl][0], afr[pl][1], afr[pl][2], afr[pl][3],
                            ab + arow * 128 + ((seg ^ (arow & 7)) << 4));
                }
#pragma unroll
                for (int nt = 0; nt < 4; ++nt)
                    MMA_BF16(acc[mt][nt], afr[0], bfr[0][nt]);   // hi*hi
#pragma unroll
                for (int nt = 0; nt < 4; ++nt)
                    MMA_BF16(acc[mt][nt], afr[0], bfr[1][nt]);   // hi*lo
#pragma unroll
                for (int nt = 0; nt < 4; ++nt)
                    MMA_BF16(acc[mt][nt], afr[1], bfr[0][nt]);   // lo*hi
            }
        }
    }
    __syncthreads();

    // ---------------- epilogue ----------------
    const int r0 = wm * 64 + (lane >> 2);
    const int c0 = wn * 32 + (lane & 3) * 2;

    if (ACT == 1) {
#pragma unroll
        for (int mt = 0; mt < 4; ++mt)
#pragma unroll
            for (int nt = 0; nt < 4; ++nt) {
                const int gc = n0 + c0 + nt * 8;
                const float bb0 = __ldg(bias + gc);
                const float bb1 = __ldg(bias + gc + 1);
#pragma unroll
                for (int h = 0; h < 2; ++h) {
                    const int row = m0 + r0 + mt * 16 + 8 * h;
                    float v0 = fmaxf(acc[mt][nt][2 * h] + bb0, 0.f);
                    float v1 = fmaxf(acc[mt][nt][2 * h + 1] + bb1, 0.f);
                    bf16 h0 = __float2bfloat16(v0), h1 = __float2bfloat16(v1);
                    bf16 l0 = __float2bfloat16(v0 - __bfloat162float(h0));
                    bf16 l1 = __float2bfloat16(v1 - __bfloat162float(h1));
                    size_t off = (size_t)row * 1024 + pkoff(gc);
                    *(bf162*)(Opk + off)      = __halves2bfloat162(h0, h1);
                    *(bf162*)(Opk + off + 32) = __halves2bfloat162(l0, l1);
                }
            }
    } else {
        float* stage = (float*)smem;          // 128 x 81 floats (reuse bufs)
#pragma unroll
        for (int mt = 0; mt < 4; ++mt)
#pragma unroll
            for (int nt = 0; nt < 4; ++nt) {
                const int col = c0 + nt * 8;
                if (col >= 80) continue;
#pragma unroll
                for (int h = 0; h < 2; ++h) {
                    const int row = r0 + mt * 16 + 8 * h;
                    if (col < OUTC)
                        stage[row * 81 + col] =
                            softplusf(acc[mt][nt][2 * h] + __ldg(bias + col));
                    if (col + 1 < OUTC)
                        stage[row * 81 + col + 1] =
                            softplusf(acc[mt][nt][2 * h + 1] + __ldg(bias + col + 1));
                }
            }
        __syncthreads();

        for (int i = tid; i < 128 * 144; i += 256) {
            int r = i / 144;
            int e = i - r * 144;
            int ii = e / 12;
            int kk = e - ii * 12;
            int mn = ii < kk ? ii : kk;
            const float* Li = stage + r * 81 + ((ii * (ii + 1)) >> 1);
            const float* Lk = stage + r * 81 + ((kk * (kk + 1)) >> 1);
            float a = 0.f;
#pragma unroll 4
            for (int j = 0; j <= mn; ++j) a = fmaf(Li[j], Lk[j], a);
            dst[(size_t)m0 * 144 + i] = a;
        }
        if (tid < 128)
            dst[(size_t)BATCH * 144 + m0 + tid] = stage[tid * 81 + TRI];
    }
}

// ---------------- launch ----------------------------------------------------
extern "C" void kernel_launch(void* const* d_in, const int* in_sizes, int n_in,
                              void* d_out, int out_size)
{
    const float* x  = (const float*)d_in[0];
    const float* W1 = (const float*)d_in[1];
    const float* b1 = (const float*)d_in[2];
    const float* W2 = (const float*)d_in[3];
    const float* b2 = (const float*)d_in[4];
    const float* W3 = (const float*)d_in[5];
    const float* b3 = (const float*)d_in[6];
    float* out = (float*)d_out;

    bf16 *h1pk, *h2pk, *w2pk, *w3pk;
    cudaGetSymbolAddress((void**)&h1pk, g_h1pk);
    cudaGetSymbolAddress((void**)&h2pk, g_h2pk);
    cudaGetSymbolAddress((void**)&w2pk, g_w2pk);
    cudaGetSymbolAddress((void**)&w3pk, g_w3pk);

    conv_w2<<<(HID * HID) / 256, 256>>>(W2);
    conv_w3<<<(128 * HID) / 256, 256>>>(W3);
    l1_kernel<<<BATCH / 64, 256>>>(x, W1, b1, h1pk);

    constexpr int SMEM = 98304;          // 3 stages x 32KB
    cudaFuncSetAttribute(mma_gemm<1>,
                         cudaFuncAttributeMaxDynamicSharedMemorySize, SMEM);
    cudaFuncSetAttribute(mma_gemm<2>,
                         cudaFuncAttributeMaxDynamicSharedMemorySize, SMEM);

    // Layer 2: h2 = relu(h1 @ W2 + b2)
    mma_gemm<1><<<dim3(4, BATCH / 128), 256, SMEM>>>(h1pk, w2pk, b2, h2pk, nullptr);
    // Layer 3 fused: softplus + L@L^T + c
    mma_gemm<2><<<dim3(1, BATCH / 128), 256, SMEM>>>(h2pk, w3pk, b3, nullptr, out);
}

// round 6
// speedup vs baseline: 1.5546x; 1.0561x over previous
#include <cuda_runtime.h>
#include <cuda_bf16.h>
#include <math.h>
#include <stdint.h>

#define BATCH 262144
#define HID 512
#define NDIM 12
#define TRI 78
#define OUTC 79

typedef __nv_bfloat16 bf16;
typedef __nv_bfloat162 bf162;

// Packed operand layout: row-major, width 1024 bf16 per row.
// col offset for k: (k/32)*64 + (k%32) -> hi plane; +32 -> lo plane.
__device__ bf16 g_h1pk[(size_t)BATCH * 1024];   // 512 MB
__device__ bf16 g_h2pk[(size_t)BATCH * 1024];   // 512 MB
__device__ bf16 g_w2pk[(size_t)HID * 1024];     // 1 MB   (rows = out-col n)
__device__ bf16 g_w3pk[(size_t)96 * 1024];      // 192 KB (rows n, zero-pad >=79)

#define SWZ(o) ((o) ^ (((o) >> 3) & 0x70))

__device__ __forceinline__ uint32_t smem_u32(const void* p) {
    uint32_t a;
    asm("{ .reg .u64 t; cvta.to.shared.u64 t, %1; cvt.u32.u64 %0, t; }"
        : "=r"(a) : "l"(p));
    return a;
}
__device__ __forceinline__ void cp16(uint32_t dst, const void* src) {
    asm volatile("cp.async.cg.shared.global [%0], [%1], 16;"
                 :: "r"(dst), "l"(src));
}
#define CP_COMMIT() asm volatile("cp.async.commit_group;" ::: "memory")
#define CP_WAIT(n)  asm volatile("cp.async.wait_group %0;" :: "n"(n) : "memory")

#define LDSM_X4(r0, r1, r2, r3, a)                                            \
    asm volatile("ldmatrix.sync.aligned.m8n8.x4.shared.b16 {%0,%1,%2,%3}, [%4];" \
                 : "=r"(r0), "=r"(r1), "=r"(r2), "=r"(r3) : "r"(a))
#define LDSM_X2(r0, r1, a)                                                    \
    asm volatile("ldmatrix.sync.aligned.m8n8.x2.shared.b16 {%0,%1}, [%2];"    \
                 : "=r"(r0), "=r"(r1) : "r"(a))
#define MMA_BF16(c, a, b)                                                     \
    asm volatile("mma.sync.aligned.m16n8k16.row.col.f32.bf16.bf16.f32 "       \
                 "{%0,%1,%2,%3}, {%4,%5,%6,%7}, {%8,%9}, {%0,%1,%2,%3};"      \
                 : "+f"((c)[0]), "+f"((c)[1]), "+f"((c)[2]), "+f"((c)[3])     \
                 : "r"((a)[0]), "r"((a)[1]), "r"((a)[2]), "r"((a)[3]),        \
                   "r"((b)[0]), "r"((b)[1]))

static __device__ __forceinline__ float softplusf(float v) {
    return (v > 20.f) ? v : log1pf(expf(v));
}
static __device__ __forceinline__ int pkoff(int k) {
    return ((k >> 5) << 6) + (k & 31);
}

// ---------------- weight converters (transpose + hi/lo split + pack) --------
__global__ __launch_bounds__(256) void conv_w2(const float* __restrict__ W2) {
    int t = blockIdx.x * 256 + threadIdx.x;        // < 512*512
    int n = t >> 9, k = t & 511;
    float v = W2[(size_t)k * HID + n];
    bf16 h = __float2bfloat16(v);
    size_t o = (size_t)n * 1024 + pkoff(k);
    g_w2pk[o] = h;
    g_w2pk[o + 32] = __float2bfloat16(v - __bfloat162float(h));
}
__global__ __launch_bounds__(256) void conv_w3(const float* __restrict__ W3) {
    int t = blockIdx.x * 256 + threadIdx.x;        // < 96*512
    int n = t >> 9, k = t & 511;
    float v = (n < OUTC) ? W3[(size_t)k * OUTC + n] : 0.f;
    bf16 h = __float2bfloat16(v);
    size_t o = (size_t)n * 1024 + pkoff(k);
    g_w3pk[o] = h;
    g_w3pk[o + 32] = __float2bfloat16(v - __bfloat162float(h));
}

// ---------------- layer 1 (K=12) — vectorized 16B stores --------------------
__global__ __launch_bounds__(256) void l1_kernel(
    const float* __restrict__ x, const float* __restrict__ W1,
    const float* __restrict__ b1, bf16* __restrict__ hpk)
{
    __shared__ float W1s[NDIM][HID];
    __shared__ float b1s[HID];
    __shared__ float xs[64][13];
    const int tid = threadIdx.x;
    const int b0 = blockIdx.x * 64;

    for (int i = tid; i < NDIM * HID; i += 256) W1s[i / HID][i % HID] = W1[i];
    for (int i = tid; i < HID; i += 256) b1s[i] = b1[i];
    for (int i = tid; i < 64 * NDIM; i += 256)
        xs[i / NDIM][i % NDIM] = x[(size_t)b0 * NDIM + i];
    __syncthreads();

#pragma unroll 4
    for (int it = 0; it < 16; ++it) {
        int p = tid + it * 256;
        int r = p >> 6;
        int c = (p & 63) * 8;
        float a[8];
#pragma unroll
        for (int j = 0; j < 8; ++j) a[j] = b1s[c + j];
#pragma unroll
        for (int k = 0; k < NDIM; ++k) {
            float xv = xs[r][k];
#pragma unroll
            for (int j = 0; j < 8; ++j)
                a[j] = fmaf(xv, W1s[k][c + j], a[j]);
        }
        __align__(16) bf162 hb[4], lb[4];
#pragma unroll
        for (int j = 0; j < 4; ++j) {
            float v0 = fmaxf(a[2 * j], 0.f), v1 = fmaxf(a[2 * j + 1], 0.f);
            bf16 h0 = __float2bfloat16(v0), h1 = __float2bfloat16(v1);
            hb[j] = __halves2bfloat162(h0, h1);
            lb[j] = __halves2bfloat162(
                __float2bfloat16(v0 - __bfloat162float(h0)),
                __float2bfloat16(v1 - __bfloat162float(h1)));
        }
        size_t base = (size_t)(b0 + r) * 1024 + pkoff(c);
        *(uint4*)(hpk + base)      = *(uint4*)hb;
        *(uint4*)(hpk + base + 32) = *(uint4*)lb;
    }
}

// ---------------- GEMM2 (R3-proven): relu(h1 @ W2^T + b2) -> packed h2 ------
__global__ __launch_bounds__(256, 2) void gemm2(
    const bf16* __restrict__ Apk, const bf16* __restrict__ Bpk,
    const float* __restrict__ bias, bf16* __restrict__ Opk)
{
    extern __shared__ char smem[];
    const uint32_t sb = smem_u32(smem);
    const int tid = threadIdx.x;
    const int lane = tid & 31;
    const int wid = tid >> 5;
    const int wm = wid >> 2;
    const int wn = wid & 3;
    const int m0 = blockIdx.y * 128;
    const int n0 = blockIdx.x * 128;

    float acc[4][4][4];
#pragma unroll
    for (int i = 0; i < 4; i++)
#pragma unroll
        for (int j = 0; j < 4; j++)
#pragma unroll
            for (int k = 0; k < 4; k++) acc[i][j][k] = 0.f;

    const bf16* Abase = Apk + (size_t)m0 * 1024;
    const bf16* Bbase = Bpk + (size_t)n0 * 1024;

    auto load_chunk = [&](int c, int buf) {
        uint32_t ab = sb + (buf ? 16384 : 0);
        uint32_t bb = sb + 32768 + (buf ? 16384 : 0);
        const bf16* As = Abase + c * 64;
        const bf16* Bs = Bbase + c * 64;
#pragma unroll
        for (int it = 0; it < 8; ++it) {
            int u = tid + it * 256;
            int half = u >> 10;
            int v = u & 1023;
            int r = v >> 3, q = v & 7;
            const bf16* s = (half ? Bs : As) + (size_t)r * 1024 + q * 8;
            cp16((half ? bb : ab) + SWZ(r * 128 + q * 16), s);
        }
        CP_COMMIT();
    };

    load_chunk(0, 0);

    for (int c = 0; c < 16; ++c) {
        CP_WAIT(0);
        __syncthreads();
        if (c < 15) load_chunk(c + 1, (c + 1) & 1);

        const int buf = c & 1;
        const uint32_t ab = sb + (buf ? 16384 : 0);
        const uint32_t bb = sb + 32768 + (buf ? 16384 : 0);

#pragma unroll
        for (int ks = 0; ks < 2; ++ks) {
            uint32_t bfr[2][4][2];
            const int brow0 = wn * 32 + (lane & 7);
            const int bsel = (lane >> 3) & 1;
#pragma unroll
            for (int pl = 0; pl < 2; ++pl)
#pragma unroll
                for (int nt = 0; nt < 4; ++nt) {
                    int row = brow0 + nt * 8;
                    int seg = pl * 4 + ks * 2 + bsel;
                    LDSM_X2(bfr[pl][nt][0], bfr[pl][nt][1],
                            bb + row * 128 + ((seg ^ (row & 7)) << 4));
                }
#pragma unroll
            for (int mt = 0; mt < 4; ++mt) {
                uint32_t afr[2][4];
                const int arow = wm * 64 + mt * 16 + (lane & 15);
                const int asel = lane >> 4;
#pragma unroll
                for (int pl = 0; pl < 2; ++pl) {
                    int seg = pl * 4 + ks * 2 + asel;
                    LDSM_X4(afr[pl][0], afr[pl][1], afr[pl][2], afr[pl][3],
                            ab + arow * 128 + ((seg ^ (arow & 7)) << 4));
                }
#pragma unroll
                for (int nt = 0; nt < 4; ++nt)
                    MMA_BF16(acc[mt][nt], afr[0], bfr[0][nt]);   // hi*hi
#pragma unroll
                for (int nt = 0; nt < 4; ++nt)
                    MMA_BF16(acc[mt][nt], afr[0], bfr[1][nt]);   // hi*lo
#pragma unroll
                for (int nt = 0; nt < 4; ++nt)
                    MMA_BF16(acc[mt][nt], afr[1], bfr[0][nt]);   // lo*hi
            }
        }
        __syncthreads();
    }

    const int r0 = wm * 64 + (lane >> 2);
    const int c0 = wn * 32 + (lane & 3) * 2;
#pragma unroll
    for (int mt = 0; mt < 4; ++mt)
#pragma unroll
        for (int nt = 0; nt < 4; ++nt) {
            const int gc = n0 + c0 + nt * 8;
            const float bb0 = __ldg(bias + gc);
            const float bb1 = __ldg(bias + gc + 1);
#pragma unroll
            for (int h = 0; h < 2; ++h) {
                const int row = m0 + r0 + mt * 16 + 8 * h;
                float v0 = fmaxf(acc[mt][nt][2 * h] + bb0, 0.f);
                float v1 = fmaxf(acc[mt][nt][2 * h + 1] + bb1, 0.f);
                bf16 h0 = __float2bfloat16(v0), h1 = __float2bfloat16(v1);
                bf16 l0 = __float2bfloat16(v0 - __bfloat162float(h0));
                bf16 l1 = __float2bfloat16(v1 - __bfloat162float(h1));
                size_t off = (size_t)row * 1024 + pkoff(gc);
                *(bf162*)(Opk + off)      = __halves2bfloat162(h0, h1);
                *(bf162*)(Opk + off + 32) = __halves2bfloat162(l0, l1);
            }
        }
}

// ---------------- GEMM3: N-tile 96 (nt=3), fused softplus + L@L^T + c -------
// smem: A0@0(16K), A1@16K, B0@32K(12K), B1@44K; total 56K. Stage reuses base.
__global__ __launch_bounds__(256, 2) void gemm3_mmt(
    const bf16* __restrict__ Apk, const bf16* __restrict__ Bpk,
    const float* __restrict__ bias, float* __restrict__ dst)
{
    extern __shared__ char smem[];
    const uint32_t sb = smem_u32(smem);
    const int tid = threadIdx.x;
    const int lane = tid & 31;
    const int wid = tid >> 5;
    const int wm = wid >> 2;        // 0..1 (m band of 64)
    const int wn = wid & 3;         // 0..3 (n band of 24)
    const int m0 = blockIdx.y * 128;

    float acc[4][3][4];
#pragma unroll
    for (int i = 0; i < 4; i++)
#pragma unroll
        for (int j = 0; j < 3; j++)
#pragma unroll
            for (int k = 0; k < 4; k++) acc[i][j][k] = 0.f;

    const bf16* Abase = Apk + (size_t)m0 * 1024;

    auto load_chunk = [&](int c, int buf) {
        uint32_t ab = sb + (buf ? 16384 : 0);
        uint32_t bb = sb + 32768 + (buf ? 12288 : 0);
        const bf16* As = Abase + c * 64;
        const bf16* Bs = Bpk + c * 64;
#pragma unroll
        for (int it = 0; it < 7; ++it) {
            int u = tid + it * 256;              // 0..1791
            if (u < 1024) {
                int r = u >> 3, q = u & 7;
                cp16(ab + SWZ(r * 128 + q * 16), As + (size_t)r * 1024 + q * 8);
            } else {
                int v = u - 1024;                // < 768
                int r = v >> 3, q = v & 7;
                cp16(bb + SWZ(r * 128 + q * 16), Bs + (size_t)r * 1024 + q * 8);
            }
        }
        CP_COMMIT();
    };

    load_chunk(0, 0);

    for (int c = 0; c < 16; ++c) {
        CP_WAIT(0);
        __syncthreads();
        if (c < 15) load_chunk(c + 1, (c + 1) & 1);

        const int buf = c & 1;
        const uint32_t ab = sb + (buf ? 16384 : 0);
        const uint32_t bb = sb + 32768 + (buf ? 12288 : 0);

#pragma unroll
        for (int ks = 0; ks < 2; ++ks) {
            uint32_t bfr[2][3][2];
            const int brow0 = wn * 24 + (lane & 7);
            const int bsel = (lane >> 3) & 1;
#pragma unroll
            for (int pl = 0; pl < 2; ++pl)
#pragma unroll
                for (int nt = 0; nt < 3; ++nt) {
                    int row = brow0 + nt * 8;
                    int seg = pl * 4 + ks * 2 + bsel;
                    LDSM_X2(bfr[pl][nt][0], bfr[pl][nt][1],
                            bb + row * 128 + ((seg ^ (row & 7)) << 4));
                }
#pragma unroll
            for (int mt = 0; mt < 4; ++mt) {
                uint32_t afr[2][4];
                const int arow = wm * 64 + mt * 16 + (lane & 15);
                const int asel = lane >> 4;
#pragma unroll
                for (int pl = 0; pl < 2; ++pl) {
                    int seg = pl * 4 + ks * 2 + asel;
                    LDSM_X4(afr[pl][0], afr[pl][1], afr[pl][2], afr[pl][3],
                            ab + arow * 128 + ((seg ^ (arow & 7)) << 4));
                }
#pragma unroll
                for (int nt = 0; nt < 3; ++nt)
                    MMA_BF16(acc[mt][nt], afr[0], bfr[0][nt]);
#pragma unroll
                for (int nt = 0; nt < 3; ++nt)
                    MMA_BF16(acc[mt][nt], afr[0], bfr[1][nt]);
#pragma unroll
                for (int nt = 0; nt < 3; ++nt)
                    MMA_BF16(acc[mt][nt], afr[1], bfr[0][nt]);
            }
        }
        __syncthreads();
    }

    // ---- epilogue: softplus -> smem stage (pitch 81) ----
    const int r0 = wm * 64 + (lane >> 2);
    const int c0 = wn * 24 + (lane & 3) * 2;
    float* stage = (float*)smem;
#pragma unroll
    for (int mt = 0; mt < 4; ++mt)
#pragma unroll
        for (int nt = 0; nt < 3; ++nt) {
            const int col = c0 + nt * 8;
            if (col >= 80) continue;
#pragma unroll
            for (int h = 0; h < 2; ++h) {
                const int row = r0 + mt * 16 + 8 * h;
                if (col < OUTC)
                    stage[row * 81 + col] =
                        softplusf(acc[mt][nt][2 * h] + __ldg(bias + col));
                if (col + 1 < OUTC)
                    stage[row * 81 + col + 1] =
                        softplusf(acc[mt][nt][2 * h + 1] + __ldg(bias + col + 1));
            }
        }
    __syncthreads();

    // ---- symmetric L@L^T: 2 threads per row, fully unrolled, no div ----
    {
        const int r = tid >> 1;
        const int half = tid & 1;
        const float* Lr = stage + r * 81;
        float* drow = dst + ((size_t)(m0 + r)) * 144;
#pragma unroll
        for (int ii = 0; ii < 12; ++ii) {
            if (((ii ^ half) & 1) == 0) continue;   // split rows by ii parity
            const float* Li = Lr + ((ii * (ii + 1)) >> 1);
#pragma unroll
            for (int kk = 0; kk <= ii; ++kk) {
                const float* Lk = Lr + ((kk * (kk + 1)) >> 1);
                float a = 0.f;
#pragma unroll
                for (int j = 0; j <= kk; ++j) a = fmaf(Li[j], Lk[j], a);
                drow[ii * 12 + kk] = a;
                if (kk != ii) drow[kk * 12 + ii] = a;
            }
        }
        if (tid < 128)
            dst[(size_t)BATCH * 144 + m0 + tid] = stage[tid * 81 + TRI];
    }
}

// ---------------- launch ----------------------------------------------------
extern "C" void kernel_launch(void* const* d_in, const int* in_sizes, int n_in,
                              void* d_out, int out_size)
{
    const float* x  = (const float*)d_in[0];
    const float* W1 = (const float*)d_in[1];
    const float* b1 = (const float*)d_in[2];
    const float* W2 = (const float*)d_in[3];
    const float* b2 = (const float*)d_in[4];
    const float* W3 = (const float*)d_in[5];
    const float* b3 = (const float*)d_in[6];
    float* out = (float*)d_out;

    bf16 *h1pk, *h2pk, *w2pk, *w3pk;
    cudaGetSymbolAddress((void**)&h1pk, g_h1pk);
    cudaGetSymbolAddress((void**)&h2pk, g_h2pk);
    cudaGetSymbolAddress((void**)&w2pk, g_w2pk);
    cudaGetSymbolAddress((void**)&w3pk, g_w3pk);

    conv_w2<<<(HID * HID) / 256, 256>>>(W2);
    conv_w3<<<(96 * HID) / 256, 256>>>(W3);
    l1_kernel<<<BATCH / 64, 256>>>(x, W1, b1, h1pk);

    constexpr int SMEM2 = 65536;
    constexpr int SMEM3 = 57344;
    cudaFuncSetAttribute(gemm2,
                         cudaFuncAttributeMaxDynamicSharedMemorySize, SMEM2);
    cudaFuncSetAttribute(gemm3_mmt,
                         cudaFuncAttributeMaxDynamicSharedMemorySize, SMEM3);

    gemm2<<<dim3(4, BATCH / 128), 256, SMEM2>>>(h1pk, w2pk, b2, h2pk);
    gemm3_mmt<<<dim3(1, BATCH / 128), 256, SMEM3>>>(h2pk, w3pk, b3, out);
}